// round 17
// baseline (speedup 1.0000x reference)
#include <cuda_runtime.h>

#define NB    32768
#define N_RX  8

// SYMS = {-3,-1,1,3}/sqrt(5)
#define S_M3 (-1.3416407864998738f)
#define S_M1 (-0.44721359549995793f)
#define S_P1 ( 0.44721359549995793f)
#define S_P3 ( 1.3416407864998738f)
#define LOG2E 1.4426950408889634f
#define LN2   0.6931471805599453f

typedef unsigned long long u64;

__device__ __forceinline__ float qsel(float a, float b, float c, float d, int i) {
    float ab = (i & 1) ? b : a;
    float cd = (i & 1) ? d : c;
    return (i & 2) ? cd : ab;
}
__device__ __forceinline__ float qselrn(float rm3, float rm1, int i) {
    float ab = (i & 1) ? rm1 : rm3;
    float cd = (i & 1) ? -rm3 : -rm1;
    return (i & 2) ? cd : ab;
}
__device__ __forceinline__ float rowmax4(const float* v) {
    return fmaxf(fmaxf(v[0], v[1]), fmaxf(v[2], v[3]));
}
__device__ __forceinline__ float ex2a(float x) {
    float y; asm("ex2.approx.ftz.f32 %0, %1;" : "=f"(y) : "f"(x)); return y;
}
__device__ __forceinline__ float lg2a(float x) {
    float y; asm("lg2.approx.ftz.f32 %0, %1;" : "=f"(y) : "f"(x)); return y;
}
__device__ __forceinline__ float rcpa(float x) {
    float y; asm("rcp.approx.ftz.f32 %0, %1;" : "=f"(y) : "f"(x)); return y;
}
// multiply + saturate to [0,1] in ONE instruction; operands >=0 so sat == min(v,1)
__device__ __forceinline__ float mulsat(float a, float b) {
    float y; asm("mul.rn.sat.f32 %0, %1, %2;" : "=f"(y) : "f"(a), "f"(b)); return y;
}
__device__ __forceinline__ u64 pk2(float lo, float hi) {
    u64 d; asm("mov.b64 %0, {%1, %2};" : "=l"(d) : "f"(lo), "f"(hi)); return d;
}
__device__ __forceinline__ void upk2(float& lo, float& hi, u64 d) {
    asm("mov.b64 {%0, %1}, %2;" : "=f"(lo), "=f"(hi) : "l"(d));
}
__device__ __forceinline__ u64 mul2(u64 a, u64 b) {
    u64 d; asm("mul.rn.f32x2 %0, %1, %2;" : "=l"(d) : "l"(a), "l"(b)); return d;
}
__device__ __forceinline__ u64 fma2(u64 a, u64 b, u64 c) {
    u64 d; asm("fma.rn.f32x2 %0, %1, %2, %3;" : "=l"(d) : "l"(a), "l"(b), "l"(c)); return d;
}

// ---- Enumeration: fills prod2[8]; outputs Cp, qz, nSB for finalize ----
__device__ __forceinline__ void enum_item(
    const float4* __restrict__ Gv, float rho2,
    float rs0, float rs1, float rm3, float rm1,
    u64 prod2[8], float& Cp, float& qz, float& nSB)
{
    const u64 NH2  = pk2(-0.5f, -0.5f);
    const u64 ONE2 = pk2(1.0f, 1.0f);
    #pragma unroll
    for (int p = 0; p < 8; p++) prod2[p] = ONE2;
    float SB = 0.f, SGZ = 0.f, SGW = 0.f;
    #pragma unroll
    for (int r = 0; r < N_RX; r++) {
        float4 g = Gv[r];
        float basen = fmaf(g.x, rs0, g.y * rs1);
        SB += basen; SGZ += g.z; SGW += g.w;
        float t0 = fmaf( g.z, rm3, basen);
        float t1 = fmaf( g.z, rm1, basen);
        float t2 = fmaf(-g.z, rm1, basen);
        float t3 = fmaf(-g.z, rm3, basen);
        float cb = g.w * rm1;
        float A0 = ex2a(t0), A1 = ex2a(t1), A2 = ex2a(t2), A3 = ex2a(t3);
        float D  = ex2a(cb), iD = rcpa(D);
        float D3 = (D * D) * D, iD3 = (iD * iD) * iD;
        const float As[4] = {A0, A1, A2, A3};
        const float Cs[4] = {D3, D, iD, iD3};
        #pragma unroll
        for (int p = 0; p < 8; p++) {          // p = i2*2 + (i3>>1)
            float A = As[p >> 1];
            float elo = mulsat(A, Cs[(p & 1) * 2]);
            float ehi = mulsat(A, Cs[(p & 1) * 2 + 1]);
            u64 e2 = pk2(elo, ehi);
            u64 h2 = fma2(NH2, e2, ONE2);
            prod2[p] = mul2(prod2[p], mul2(e2, h2));
        }
    }
    Cp  = rho2 * SGW;
    qz  = SGZ * rho2;
    nSB = -SB;
}

__device__ __forceinline__ void finalize_lp2(
    const u64 prod2[8], float Cp, float qz, float nSB, float lp2[16])
{
    const float SY[4] = {S_M3, S_M1, S_P1, S_P3};
    #pragma unroll
    for (int p = 0; p < 8; p++) {
        const int i2  = p >> 1;
        const int i3a = (p & 1) * 2;
        float T = fmaf(qz, SY[i2], nSB);
        float plo, phi;
        upk2(plo, phi, prod2[p]);
        lp2[i2 * 4 + i3a]     = fmaf(Cp, SY[i3a],     T) + lg2a(fmaxf(plo, 1e-37f));
        lp2[i2 * 4 + i3a + 1] = fmaf(Cp, SY[i3a + 1], T) + lg2a(fmaxf(phi, 1e-37f));
    }
}

// ---- Sequential 4-transmitter update; returns this lane's output element (pre-*LN2).
// Lane writes out element idx hl: row = hl>>2, col = hl&3.
__device__ __forceinline__ float update_item(
    const float4* __restrict__ Lv, const float lp2[16], float alpha,
    int i0, int i1, int hl, int base, int bit0, int bit1)
{
    const unsigned FULL = 0xffffffffu;
    const float oma = 1.0f - alpha;

    // Rows 0,1 distributed
    float4 v0 = Lv[0];
    float lq0own = qsel(v0.x, v0.y, v0.z, v0.w, i0) * LOG2E;
    float f0 = ex2a(lq0own);
    float4 v1 = Lv[1];
    float lq1own = qsel(v1.x, v1.y, v1.z, v1.w, i1) * LOG2E;
    float m1 = lq1own;
    m1 = fmaxf(m1, __shfl_xor_sync(FULL, m1, 1));
    m1 = fmaxf(m1, __shfl_xor_sync(FULL, m1, 2));
    float f1 = ex2a(lq1own - m1);
    float S1 = f1 + __shfl_xor_sync(FULL, f1, 1);
    S1 += __shfl_xor_sync(FULL, S1, 2);

    // Rows 2,3 replicated
    float lq[2][4], off2, off3;
    {
        float4 v = Lv[2];
        lq[0][0] = v.x * LOG2E; lq[0][1] = v.y * LOG2E;
        lq[0][2] = v.z * LOG2E; lq[0][3] = v.w * LOG2E;
        off2 = rowmax4(lq[0]);
    }
    {
        float4 v = Lv[3];
        lq[1][0] = v.x * LOG2E; lq[1][1] = v.y * LOG2E;
        lq[1][2] = v.z * LOG2E; lq[1][3] = v.w * LOG2E;
        off3 = rowmax4(lq[1]);
    }
    float e2n[4], S2, S3, ul[4];
    e2n[0] = ex2a(lq[0][0]-off2); e2n[1] = ex2a(lq[0][1]-off2);
    e2n[2] = ex2a(lq[0][2]-off2); e2n[3] = ex2a(lq[0][3]-off2);
    S2 = (e2n[0] + e2n[1]) + (e2n[2] + e2n[3]);
    {
        float e0 = ex2a(lq[1][0]-off3), e1 = ex2a(lq[1][1]-off3);
        float e2 = ex2a(lq[1][2]-off3), e3 = ex2a(lq[1][3]-off3);
        S3 = (e0 + e1) + (e2 + e3);
        #pragma unroll
        for (int c = 0; c < 4; c++)
            ul[c] = fmaf(e3, lp2[c*4+3], fmaf(e2, lp2[c*4+2], fmaf(e1, lp2[c*4+1], e0 * lp2[c*4+0])));
    }
    float sum_wl = fmaf(e2n[3], ul[3], fmaf(e2n[2], ul[2], fmaf(e2n[1], ul[1], e2n[0] * ul[0])));
    float S23 = S2 * S3;

    // xi = 0 : bucket i0 (bits 2,3); reduce bits 0,1.
    float d0, S0n;
    {
        float a = f1 * sum_wl;
        a += __shfl_xor_sync(FULL, a, 1);
        a += __shfl_xor_sync(FULL, a, 2);
        float sc = alpha * rcpa(S1 * S23);
        float nv = fmaf(oma, lq0own, sc * a);
        float o = nv;
        o = fmaxf(o, __shfl_xor_sync(FULL, o, 4));
        o = fmaxf(o, __shfl_xor_sync(FULL, o, 8));
        d0 = nv - o;
        f0 = ex2a(d0);
        S0n = f0 + __shfl_xor_sync(FULL, f0, 4);
        S0n += __shfl_xor_sync(FULL, S0n, 8);
    }

    // xi = 1 : bucket i1 (bits 0,1); reduce bits 2,3.
    float d1, S1n, f01;
    {
        float a = f0 * sum_wl;
        a += __shfl_xor_sync(FULL, a, 4);
        a += __shfl_xor_sync(FULL, a, 8);
        float sc = alpha * rcpa(S0n * S23);
        float nv = fmaf(oma, lq1own - m1, sc * a);
        float o = nv;
        o = fmaxf(o, __shfl_xor_sync(FULL, o, 1));
        o = fmaxf(o, __shfl_xor_sync(FULL, o, 2));
        d1 = nv - o;
        float e1n = ex2a(d1);
        S1n = e1n + __shfl_xor_sync(FULL, e1n, 1);
        S1n += __shfl_xor_sync(FULL, S1n, 2);
        f01 = f0 * e1n;
    }

    // xi = 2 : bucket i2; fold onto hl bits 0,1, reduce bits 2,3. Full row.
    float e2w[4], S2n, S01;
    {
        float a0 = f01 * ul[0], a1 = f01 * ul[1], a2v = f01 * ul[2], a3v = f01 * ul[3];
        float kA = bit0 ? a1 : a0,   sA = bit0 ? a0 : a1;
        float kB = bit0 ? a3v : a2v, sB = bit0 ? a2v : a3v;
        float rA = kA + __shfl_xor_sync(FULL, sA, 1);
        float rB = kB + __shfl_xor_sync(FULL, sB, 1);
        float k2 = bit1 ? rB : rA,   s2 = bit1 ? rA : rB;
        float a = k2 + __shfl_xor_sync(FULL, s2, 2);    // bucket hl&3
        a += __shfl_xor_sync(FULL, a, 4);
        a += __shfl_xor_sync(FULL, a, 8);
        float b0 = __shfl_sync(FULL, a, base + 0);
        float b1 = __shfl_sync(FULL, a, base + 1);
        float b2 = __shfl_sync(FULL, a, base + 2);
        float b3 = __shfl_sync(FULL, a, base + 3);
        S01 = S0n * S1n;
        float sc = alpha * rcpa(S01 * S3);
        float o = off2;
        lq[0][0] = fmaf(oma, lq[0][0] - o, sc * b0);
        lq[0][1] = fmaf(oma, lq[0][1] - o, sc * b1);
        lq[0][2] = fmaf(oma, lq[0][2] - o, sc * b2);
        lq[0][3] = fmaf(oma, lq[0][3] - o, sc * b3);
        off2 = rowmax4(lq[0]);
        e2w[0] = ex2a(lq[0][0]-off2); e2w[1] = ex2a(lq[0][1]-off2);
        e2w[2] = ex2a(lq[0][2]-off2); e2w[3] = ex2a(lq[0][3]-off2);
        S2n = (e2w[0] + e2w[1]) + (e2w[2] + e2w[3]);
    }

    // xi = 3 : bucket i3; fold + reduce bits 2,3. Full row.
    {
        float v0a = 0.f, v1a = 0.f, v2a = 0.f, v3a = 0.f;
        #pragma unroll
        for (int c = 0; c < 4; c++) {
            v0a = fmaf(e2w[c], lp2[c*4+0], v0a);
            v1a = fmaf(e2w[c], lp2[c*4+1], v1a);
            v2a = fmaf(e2w[c], lp2[c*4+2], v2a);
            v3a = fmaf(e2w[c], lp2[c*4+3], v3a);
        }
        v0a *= f01; v1a *= f01; v2a *= f01; v3a *= f01;
        float kA = bit0 ? v1a : v0a, sA = bit0 ? v0a : v1a;
        float kB = bit0 ? v3a : v2a, sB = bit0 ? v2a : v3a;
        float rA = kA + __shfl_xor_sync(FULL, sA, 1);
        float rB = kB + __shfl_xor_sync(FULL, sB, 1);
        float k2 = bit1 ? rB : rA, s2 = bit1 ? rA : rB;
        float a = k2 + __shfl_xor_sync(FULL, s2, 2);    // bucket hl&3
        a += __shfl_xor_sync(FULL, a, 4);
        a += __shfl_xor_sync(FULL, a, 8);
        float b0 = __shfl_sync(FULL, a, base + 0);
        float b1 = __shfl_sync(FULL, a, base + 1);
        float b2 = __shfl_sync(FULL, a, base + 2);
        float b3 = __shfl_sync(FULL, a, base + 3);
        float sc = alpha * rcpa(S01 * S2n);
        float o = off3;
        lq[1][0] = fmaf(oma, lq[1][0] - o, sc * b0);
        lq[1][1] = fmaf(oma, lq[1][1] - o, sc * b1);
        lq[1][2] = fmaf(oma, lq[1][2] - o, sc * b2);
        lq[1][3] = fmaf(oma, lq[1][3] - o, sc * b3);
        off3 = rowmax4(lq[1]);
    }

    // Gather this lane's output element: row hl>>2, col hl&3
    float g0 = __shfl_sync(FULL, d0, base + ((hl & 3) << 2));  // row0 col at lane i0==col
    float g1 = __shfl_sync(FULL, d1, base + (hl & 3));         // row1 col at lane i1==col
    float q2 = qsel(lq[0][0], lq[0][1], lq[0][2], lq[0][3], hl) - off2;
    float q3 = qsel(lq[1][0], lq[1][1], lq[1][2], lq[1][3], hl) - off3;
    return qsel(g0, g1, q2, q3, hl >> 2);
}

__global__ __launch_bounds__(128, 5)
void mfnet_layer_kernel(const float* __restrict__ log_qi_in,
                        const float* __restrict__ G,
                        const float* __restrict__ sqrt_2rho,
                        const float* __restrict__ alpha_ptr,
                        float* __restrict__ out)
{
    const int gtid = blockIdx.x * blockDim.x + threadIdx.x;
    const int w    = gtid >> 5;
    const int lane = gtid & 31;
    const int half = lane >> 4;
    const int hl   = lane & 15;
    const int base = lane & 16;

    // Four items per warp: pair A = {4w, 4w+1}, pair B = {4w+2, 4w+3}
    const int bA = 4 * w + half;
    const int bB = bA + 2;

    const float alpha = __ldg(alpha_ptr);

    const int i0 = hl >> 2;
    const int i1 = hl & 3;
    const int bit0 = hl & 1;
    const int bit1 = (hl >> 1) & 1;

    // ---- Item A: enumeration ----
    const float rho2A  = __ldg(&sqrt_2rho[bA]) * LOG2E;
    const float rho2nA = -rho2A;
    const float rm3A = rho2nA * S_M3, rm1A = rho2nA * S_M1;
    const float rs0A = qselrn(rm3A, rm1A, i0);
    const float rs1A = qselrn(rm3A, rm1A, i1);
    u64 prodA[8];
    float CpA, qzA, nSBA;
    enum_item(reinterpret_cast<const float4*>(G) + (size_t)bA * N_RX, rho2A,
              rs0A, rs1A, rm3A, rm1A, prodA, CpA, qzA, nSBA);
    float lp2A[16];
    finalize_lp2(prodA, CpA, qzA, nSBA, lp2A);

    // ---- Item B: enumeration (independent of update A; ptxas interleaves) ----
    const float rho2B  = __ldg(&sqrt_2rho[bB]) * LOG2E;
    const float rho2nB = -rho2B;
    const float rm3B = rho2nB * S_M3, rm1B = rho2nB * S_M1;
    const float rs0B = qselrn(rm3B, rm1B, i0);
    const float rs1B = qselrn(rm3B, rm1B, i1);
    u64 prodB[8];
    float CpB, qzB, nSBB;
    enum_item(reinterpret_cast<const float4*>(G) + (size_t)bB * N_RX, rho2B,
              rs0B, rs1B, rm3B, rm1B, prodB, CpB, qzB, nSBB);

    // ---- Update A (latency-heavy; overlaps with enum B issue) ----
    float valA = update_item(reinterpret_cast<const float4*>(log_qi_in) + (size_t)bA * 4,
                             lp2A, alpha, i0, i1, hl, base, bit0, bit1);

    // ---- Finalize + update B ----
    float lp2B[16];
    finalize_lp2(prodB, CpB, qzB, nSBB, lp2B);
    float valB = update_item(reinterpret_cast<const float4*>(log_qi_in) + (size_t)bB * 4,
                             lp2B, alpha, i0, i1, hl, base, bit0, bit1);

    // ---- Stores: one float per lane per item, fully coalesced ----
    out[(size_t)bA * 16 + hl] = valA * LN2;
    out[(size_t)bB * 16 + hl] = valB * LN2;
}

extern "C" void kernel_launch(void* const* d_in, const int* in_sizes, int n_in,
                              void* d_out, int out_size)
{
    const float* log_qi    = (const float*)d_in[0]; // (N,4,4)
    const float* G         = (const float*)d_in[1]; // (N,8,4)
    const float* sqrt_2rho = (const float*)d_in[2]; // (N,)
    // d_in[3] = n_var, unused by reference
    const float* alpha     = (const float*)d_in[4]; // scalar

    float* out = (float*)d_out;

    // 4 items per warp -> NB/4 warps
    const int threads = 128;
    const int blocks  = (NB / 4) * 32 / threads;   // 2048
    mfnet_layer_kernel<<<blocks, threads>>>(log_qi, G, sqrt_2rho, alpha, out);
}